// round 1
// baseline (speedup 1.0000x reference)
#include <cuda_runtime.h>

#define D_MODEL 1024
#define N_HEADS 16
#define DK      64
#define SEQ     2048
#define BATCH   2
#define ROWS    (BATCH * SEQ)          /* 4096 */
#define LN_EPS  1e-5f

#define SY ((long long)ROWS * D_MODEL)                         /* 4194304  */
#define SA ((long long)BATCH * N_HEADS * SEQ * SEQ)            /* 134217728 */

// ---------------- scratch (static device globals: no runtime alloc) --------
__device__ float g_q  [ROWS * D_MODEL];
__device__ float g_k  [ROWS * D_MODEL];
__device__ float g_v  [ROWS * D_MODEL];
__device__ float g_ctx[ROWS * D_MODEL];
__device__ float g_o  [ROWS * D_MODEL];
__device__ float g_sc [(size_t)BATCH * N_HEADS * SEQ * SEQ];   // 512 MB

// ---------------- reductions ----------------------------------------------
__device__ __forceinline__ float warpReduceSum(float v) {
#pragma unroll
    for (int o = 16; o > 0; o >>= 1) v += __shfl_xor_sync(0xffffffffu, v, o);
    return v;
}
__device__ __forceinline__ float warpReduceMax(float v) {
#pragma unroll
    for (int o = 16; o > 0; o >>= 1) v = fmaxf(v, __shfl_xor_sync(0xffffffffu, v, o));
    return v;
}
__device__ __forceinline__ float blockReduceSum(float v) {
    __shared__ float sh[8];
    __shared__ float res;
    int lane = threadIdx.x & 31, w = threadIdx.x >> 5;
    v = warpReduceSum(v);
    if (lane == 0) sh[w] = v;
    __syncthreads();
    if (w == 0) {
        float t = (lane < 8) ? sh[lane] : 0.0f;
        t = warpReduceSum(t);
        if (lane == 0) res = t;
    }
    __syncthreads();
    float r = res;
    __syncthreads();   // protect sh/res for back-to-back calls
    return r;
}
__device__ __forceinline__ float blockReduceMax(float v) {
    __shared__ float sh[8];
    __shared__ float res;
    int lane = threadIdx.x & 31, w = threadIdx.x >> 5;
    v = warpReduceMax(v);
    if (lane == 0) sh[w] = v;
    __syncthreads();
    if (w == 0) {
        float t = (lane < 8) ? sh[lane] : -3.4e38f;
        t = warpReduceMax(t);
        if (lane == 0) res = t;
    }
    __syncthreads();
    float r = res;
    __syncthreads();
    return r;
}

// ---------------- GEMM NT: C[M,N] = alpha * A[M,K] * B[N,K]^T -------------
// 64x64 block tile, BK=16, 256 threads, 4x4 per-thread microtile.
// Batch over blockIdx.z: zb = z/H, zh = z%H; per-operand (batch,head) strides.
__global__ void __launch_bounds__(256)
gemm_nt(int M, int N, int K,
        const float* __restrict__ A, int lda, long long aSB, long long aSH,
        const float* __restrict__ B, int ldb, long long bSB, long long bSH,
        float* __restrict__ C, int ldc, long long cSB, long long cSH,
        float alpha, int H)
{
    int z = blockIdx.z;
    int zb = z / H, zh = z % H;
    A += (long long)zb * aSB + (long long)zh * aSH;
    B += (long long)zb * bSB + (long long)zh * bSH;
    C += (long long)zb * cSB + (long long)zh * cSH;

    __shared__ float As[16][64];
    __shared__ float Bs[16][64];

    int t  = threadIdx.x;
    int tx = t & 15, ty = t >> 4;
    int m0 = blockIdx.y * 64;
    int n0 = blockIdx.x * 64;

    int lr = t >> 2;           // 0..63 : row within tile
    int lk = (t & 3) * 4;      // 0,4,8,12 : k offset (float4)

    float acc[4][4] = {};

    for (int k0 = 0; k0 < K; k0 += 16) {
        float4 a4 = *(const float4*)(A + (long long)(m0 + lr) * lda + k0 + lk);
        float4 b4 = *(const float4*)(B + (long long)(n0 + lr) * ldb + k0 + lk);
        As[lk + 0][lr] = a4.x; As[lk + 1][lr] = a4.y;
        As[lk + 2][lr] = a4.z; As[lk + 3][lr] = a4.w;
        Bs[lk + 0][lr] = b4.x; Bs[lk + 1][lr] = b4.y;
        Bs[lk + 2][lr] = b4.z; Bs[lk + 3][lr] = b4.w;
        __syncthreads();
#pragma unroll
        for (int kk = 0; kk < 16; kk++) {
            float ar[4], br[4];
#pragma unroll
            for (int i = 0; i < 4; i++) ar[i] = As[kk][ty * 4 + i];
#pragma unroll
            for (int j = 0; j < 4; j++) br[j] = Bs[kk][tx * 4 + j];
#pragma unroll
            for (int i = 0; i < 4; i++)
#pragma unroll
                for (int j = 0; j < 4; j++)
                    acc[i][j] = fmaf(ar[i], br[j], acc[i][j]);
        }
        __syncthreads();
    }
#pragma unroll
    for (int i = 0; i < 4; i++) {
        float4 o;
        o.x = alpha * acc[i][0]; o.y = alpha * acc[i][1];
        o.z = alpha * acc[i][2]; o.w = alpha * acc[i][3];
        *(float4*)(C + (long long)(m0 + ty * 4 + i) * ldc + n0 + tx * 4) = o;
    }
}

// ---------------- GEMM NN: C[M,N] = A[M,K] * B[K,N] -----------------------
__global__ void __launch_bounds__(256)
gemm_nn(int M, int N, int K,
        const float* __restrict__ A, int lda, long long aSB, long long aSH,
        const float* __restrict__ B, int ldb, long long bSB, long long bSH,
        float* __restrict__ C, int ldc, long long cSB, long long cSH,
        int H)
{
    int z = blockIdx.z;
    int zb = z / H, zh = z % H;
    A += (long long)zb * aSB + (long long)zh * aSH;
    B += (long long)zb * bSB + (long long)zh * bSH;
    C += (long long)zb * cSB + (long long)zh * cSH;

    __shared__ float As[16][64];
    __shared__ float Bs[16][64];

    int t  = threadIdx.x;
    int tx = t & 15, ty = t >> 4;
    int m0 = blockIdx.y * 64;
    int n0 = blockIdx.x * 64;

    int lr = t >> 2;           // A: row within tile
    int lk = (t & 3) * 4;      // A: k offset
    int bc = (t & 15) * 4;     // B: col offset (float4)
    int bk = t >> 4;           // B: k row 0..15

    float acc[4][4] = {};

    for (int k0 = 0; k0 < K; k0 += 16) {
        float4 a4 = *(const float4*)(A + (long long)(m0 + lr) * lda + k0 + lk);
        float4 b4 = *(const float4*)(B + (long long)(k0 + bk) * ldb + n0 + bc);
        As[lk + 0][lr] = a4.x; As[lk + 1][lr] = a4.y;
        As[lk + 2][lr] = a4.z; As[lk + 3][lr] = a4.w;
        Bs[bk][bc + 0] = b4.x; Bs[bk][bc + 1] = b4.y;
        Bs[bk][bc + 2] = b4.z; Bs[bk][bc + 3] = b4.w;
        __syncthreads();
#pragma unroll
        for (int kk = 0; kk < 16; kk++) {
            float ar[4], br[4];
#pragma unroll
            for (int i = 0; i < 4; i++) ar[i] = As[kk][ty * 4 + i];
#pragma unroll
            for (int j = 0; j < 4; j++) br[j] = Bs[kk][tx * 4 + j];
#pragma unroll
            for (int i = 0; i < 4; i++)
#pragma unroll
                for (int j = 0; j < 4; j++)
                    acc[i][j] = fmaf(ar[i], br[j], acc[i][j]);
        }
        __syncthreads();
    }
#pragma unroll
    for (int i = 0; i < 4; i++) {
        float4 o;
        o.x = acc[i][0]; o.y = acc[i][1]; o.z = acc[i][2]; o.w = acc[i][3];
        *(float4*)(C + (long long)(m0 + ty * 4 + i) * ldc + n0 + tx * 4) = o;
    }
}

// ---------------- row softmax over 2048 elems; optional copy to attn out --
__global__ void __launch_bounds__(256)
softmax_rows(float* __restrict__ s, float* __restrict__ attn_out)
{
    long long row = blockIdx.x;
    float4* p4 = (float4*)(s + row * SEQ);
    int tid = threadIdx.x;

    float4 e0 = p4[tid];
    float4 e1 = p4[tid + 256];

    float m = fmaxf(fmaxf(fmaxf(e0.x, e0.y), fmaxf(e0.z, e0.w)),
                    fmaxf(fmaxf(e1.x, e1.y), fmaxf(e1.z, e1.w)));
    m = blockReduceMax(m);

    e0.x = expf(e0.x - m); e0.y = expf(e0.y - m);
    e0.z = expf(e0.z - m); e0.w = expf(e0.w - m);
    e1.x = expf(e1.x - m); e1.y = expf(e1.y - m);
    e1.z = expf(e1.z - m); e1.w = expf(e1.w - m);

    float sum = e0.x + e0.y + e0.z + e0.w + e1.x + e1.y + e1.z + e1.w;
    sum = blockReduceSum(sum);
    float inv = 1.0f / sum;

    e0.x *= inv; e0.y *= inv; e0.z *= inv; e0.w *= inv;
    e1.x *= inv; e1.y *= inv; e1.z *= inv; e1.w *= inv;

    p4[tid]       = e0;
    p4[tid + 256] = e1;
    if (attn_out) {
        float4* a4 = (float4*)(attn_out + row * SEQ);
        a4[tid]       = e0;
        a4[tid + 256] = e1;
    }
}

// ---------------- bias + residual + LayerNorm ------------------------------
__global__ void __launch_bounds__(256)
bias_res_ln(const float* __restrict__ o, const float* __restrict__ x,
            const float* __restrict__ bo, const float* __restrict__ gamma,
            const float* __restrict__ beta, float* __restrict__ y)
{
    long long row = blockIdx.x;
    int tid = threadIdx.x;
    const float4* o4 = (const float4*)(o + row * D_MODEL);
    const float4* x4 = (const float4*)(x + row * D_MODEL);
    const float4* b4 = (const float4*)bo;
    const float4* g4 = (const float4*)gamma;
    const float4* be4 = (const float4*)beta;

    float4 ov = o4[tid], xv = x4[tid], bv = b4[tid];
    float4 v;
    v.x = ov.x + xv.x + bv.x;
    v.y = ov.y + xv.y + bv.y;
    v.z = ov.z + xv.z + bv.z;
    v.w = ov.w + xv.w + bv.w;

    float s  = v.x + v.y + v.z + v.w;
    float sq = v.x * v.x + v.y * v.y + v.z * v.z + v.w * v.w;
    s  = blockReduceSum(s);
    sq = blockReduceSum(sq);

    float mean = s * (1.0f / D_MODEL);
    float var  = sq * (1.0f / D_MODEL) - mean * mean;
    float rstd = rsqrtf(var + LN_EPS);

    float4 gv = g4[tid], bev = be4[tid];
    float4 r;
    r.x = (v.x - mean) * rstd * gv.x + bev.x;
    r.y = (v.y - mean) * rstd * gv.y + bev.y;
    r.z = (v.z - mean) * rstd * gv.z + bev.z;
    r.w = (v.w - mean) * rstd * gv.w + bev.w;
    ((float4*)(y + row * D_MODEL))[tid] = r;
}

// ---------------- launch ---------------------------------------------------
extern "C" void kernel_launch(void* const* d_in, const int* in_sizes, int n_in,
                              void* d_out, int out_size)
{
    const float* x     = (const float*)d_in[0];
    const float* Wq    = (const float*)d_in[1];
    const float* Wk    = (const float*)d_in[2];
    const float* Wv    = (const float*)d_in[3];
    const float* Wo    = (const float*)d_in[4];
    const float* bo    = (const float*)d_in[5];
    const float* gamma = (const float*)d_in[6];
    const float* beta  = (const float*)d_in[7];

    float* y_out    = (float*)d_out;
    float* attn_out = nullptr;
    if ((long long)out_size >= SY + SA) {
        attn_out = y_out + SY;                 // outputs concatenated: y, attn
    } else if ((long long)out_size == SA) {
        attn_out = y_out;                      // attn-only output
        y_out = nullptr;
    }

    float *q, *k, *v, *ctx, *ob, *sc;
    cudaGetSymbolAddress((void**)&q,   g_q);
    cudaGetSymbolAddress((void**)&k,   g_k);
    cudaGetSymbolAddress((void**)&v,   g_v);
    cudaGetSymbolAddress((void**)&ctx, g_ctx);
    cudaGetSymbolAddress((void**)&ob,  g_o);
    cudaGetSymbolAddress((void**)&sc,  g_sc);

    dim3 blk(256);
    const long long SBH = (long long)SEQ * D_MODEL;   // per-batch stride in q/k/v/ctx
    const long long SSC = (long long)SEQ * SEQ;       // per-head stride in scores

    // Q/K/V projections: [4096,1024] = x[4096,1024] @ W^T
    gemm_nt<<<dim3(16, 64, 1), blk>>>(ROWS, D_MODEL, D_MODEL,
        x, D_MODEL, 0, 0, Wq, D_MODEL, 0, 0, q, D_MODEL, 0, 0, 1.0f, 1);
    gemm_nt<<<dim3(16, 64, 1), blk>>>(ROWS, D_MODEL, D_MODEL,
        x, D_MODEL, 0, 0, Wk, D_MODEL, 0, 0, k, D_MODEL, 0, 0, 1.0f, 1);
    gemm_nt<<<dim3(16, 64, 1), blk>>>(ROWS, D_MODEL, D_MODEL,
        x, D_MODEL, 0, 0, Wv, D_MODEL, 0, 0, v, D_MODEL, 0, 0, 1.0f, 1);

    // scores[bh] = Q_bh @ K_bh^T / 8   (z = b*16+h)
    gemm_nt<<<dim3(32, 32, BATCH * N_HEADS), blk>>>(SEQ, SEQ, DK,
        q, D_MODEL, SBH, DK,
        k, D_MODEL, SBH, DK,
        sc, SEQ, (long long)N_HEADS * SSC, SSC,
        0.125f, N_HEADS);

    // softmax rows (also emits attn output)
    softmax_rows<<<BATCH * N_HEADS * SEQ, blk>>>(sc, attn_out);

    // ctx[bh] = attn_bh @ V_bh   -> packed back to [B,S,H*dk]
    gemm_nn<<<dim3(1, 32, BATCH * N_HEADS), blk>>>(SEQ, DK, SEQ,
        sc, SEQ, (long long)N_HEADS * SSC, SSC,
        v, D_MODEL, SBH, DK,
        ctx, D_MODEL, SBH, DK,
        N_HEADS);

    // output projection
    gemm_nt<<<dim3(16, 64, 1), blk>>>(ROWS, D_MODEL, D_MODEL,
        ctx, D_MODEL, 0, 0, Wo, D_MODEL, 0, 0, ob, D_MODEL, 0, 0, 1.0f, 1);

    // bias + residual + layernorm -> y
    if (y_out)
        bias_res_ln<<<ROWS, blk>>>(ob, x, bo, gamma, beta, y_out);
}

// round 2
// speedup vs baseline: 2.6933x; 2.6933x over previous
#include <cuda_runtime.h>
#include <cstdint>

#define D_MODEL 1024
#define N_HEADS 16
#define DK      64
#define SEQ     2048
#define BATCH   2
#define ROWS    (BATCH * SEQ)          /* 4096 */
#define LN_EPS  1e-5f

#define SY ((long long)ROWS * D_MODEL)                         /* 4194304  */
#define SA ((long long)BATCH * N_HEADS * SEQ * SEQ)            /* 134217728 */

// ---------------- scratch (static device globals: no runtime alloc) --------
__device__ float g_q  [ROWS * D_MODEL];
__device__ float g_k  [ROWS * D_MODEL];   // reused as V^T after scores GEMM
__device__ float g_v  [ROWS * D_MODEL];
__device__ float g_ctx[ROWS * D_MODEL];
__device__ float g_o  [ROWS * D_MODEL];
__device__ float g_sc [(size_t)BATCH * N_HEADS * SEQ * SEQ];   // 512 MB

// ---------------- helpers --------------------------------------------------
__device__ __forceinline__ uint32_t f2tf32(float f) {
    uint32_t u;
    asm("cvt.rna.tf32.f32 %0, %1;" : "=r"(u) : "f"(f));
    return u;
}
__device__ __forceinline__ void cp16(void* smem, const void* g) {
    uint32_t a = (uint32_t)__cvta_generic_to_shared(smem);
    asm volatile("cp.async.cg.shared.global [%0], [%1], 16;" :: "r"(a), "l"(g));
}
__device__ __forceinline__ void cp_commit() {
    asm volatile("cp.async.commit_group;");
}
__device__ __forceinline__ void cp_wait1() {
    asm volatile("cp.async.wait_group 1;");
}

__device__ __forceinline__ float warpReduceSum(float v) {
#pragma unroll
    for (int o = 16; o > 0; o >>= 1) v += __shfl_xor_sync(0xffffffffu, v, o);
    return v;
}
__device__ __forceinline__ float warpReduceMax(float v) {
#pragma unroll
    for (int o = 16; o > 0; o >>= 1) v = fmaxf(v, __shfl_xor_sync(0xffffffffu, v, o));
    return v;
}
__device__ __forceinline__ float blockReduceSum(float v) {
    __shared__ float sh[8];
    __shared__ float res;
    int lane = threadIdx.x & 31, w = threadIdx.x >> 5;
    v = warpReduceSum(v);
    if (lane == 0) sh[w] = v;
    __syncthreads();
    if (w == 0) {
        float t = (lane < 8) ? sh[lane] : 0.0f;
        t = warpReduceSum(t);
        if (lane == 0) res = t;
    }
    __syncthreads();
    float r = res;
    __syncthreads();
    return r;
}
__device__ __forceinline__ float blockReduceMax(float v) {
    __shared__ float sh[8];
    __shared__ float res;
    int lane = threadIdx.x & 31, w = threadIdx.x >> 5;
    v = warpReduceMax(v);
    if (lane == 0) sh[w] = v;
    __syncthreads();
    if (w == 0) {
        float t = (lane < 8) ? sh[lane] : -3.4e38f;
        t = warpReduceMax(t);
        if (lane == 0) res = t;
    }
    __syncthreads();
    float r = res;
    __syncthreads();
    return r;
}

// ---------------- tf32 tensor-core GEMM NT ---------------------------------
// C[M,N] = alpha * A[M,K] * B[N,K]^T    (both operands K-major / row-major)
// BM=128 fixed, BN template (128 or 64), BK=16, 256 threads = 8 warps (2x4).
// Warp tile: 64 x (BN/4). mma.m16n8k8 tf32. 2-stage cp.async pipeline.
template<int BN>
__global__ void __launch_bounds__(256)
gemm_nt_tf32(int M, int N, int K,
             const float* __restrict__ A, int lda, long long aSB, long long aSH,
             const float* __restrict__ B, int ldb, long long bSB, long long bSH,
             float* __restrict__ C, int ldc, long long cSB, long long cSH,
             float alpha, int H)
{
    constexpr int BM  = 128;
    constexpr int BK  = 16;
    constexpr int STR = 20;          // padded k-stride: conflict-free frag loads
    constexpr int TNW = BN / 4;      // warp n extent
    constexpr int TNT = BN / 32;     // n-tiles (n8) per warp: 4 or 2

    int z = blockIdx.z;
    int zb = z / H, zh = z % H;
    A += (long long)zb * aSB + (long long)zh * aSH;
    B += (long long)zb * bSB + (long long)zh * bSH;
    C += (long long)zb * cSB + (long long)zh * cSH;

    __shared__ float As[2][BM * STR];
    __shared__ float Bs[2][BN * STR];

    int t    = threadIdx.x;
    int w    = t >> 5, lane = t & 31;
    int wm   = w >> 2, wn = w & 3;
    int g    = lane >> 2, tg = lane & 3;

    const float* Ag = A + (long long)(blockIdx.y * BM) * lda;
    const float* Bg = B + (long long)(blockIdx.x * BN) * ldb;

    int lr = t >> 2;              // 0..63
    int lc = (t & 3) * 4;         // 0,4,8,12

    float acc[4][TNT][4];
#pragma unroll
    for (int i = 0; i < 4; i++)
#pragma unroll
        for (int j = 0; j < TNT; j++)
#pragma unroll
            for (int q = 0; q < 4; q++) acc[i][j][q] = 0.0f;

    auto load_tile = [&](int kt, int s) {
        long long ko = (long long)kt * BK;
        cp16(&As[s][lr * STR + lc],        Ag + (long long)lr * lda + ko + lc);
        cp16(&As[s][(lr + 64) * STR + lc], Ag + (long long)(lr + 64) * lda + ko + lc);
        cp16(&Bs[s][lr * STR + lc],        Bg + (long long)lr * ldb + ko + lc);
        if (BN == 128)
            cp16(&Bs[s][(lr + 64) * STR + lc], Bg + (long long)(lr + 64) * ldb + ko + lc);
    };

    int KT = K / BK;
    load_tile(0, 0);
    cp_commit();

    for (int kt = 0; kt < KT; kt++) {
        if (kt + 1 < KT) load_tile(kt + 1, (kt + 1) & 1);
        cp_commit();
        cp_wait1();
        __syncthreads();

        const float* as = As[kt & 1];
        const float* bs = Bs[kt & 1];

#pragma unroll
        for (int kh = 0; kh < 2; kh++) {
            int kk = kh * 8;
            uint32_t af[4][4];
#pragma unroll
            for (int i = 0; i < 4; i++) {
                int r = wm * 64 + i * 16 + g;
                af[i][0] = f2tf32(as[r * STR + kk + tg]);
                af[i][1] = f2tf32(as[(r + 8) * STR + kk + tg]);
                af[i][2] = f2tf32(as[r * STR + kk + tg + 4]);
                af[i][3] = f2tf32(as[(r + 8) * STR + kk + tg + 4]);
            }
            uint32_t bf[TNT][2];
#pragma unroll
            for (int j = 0; j < TNT; j++) {
                int n = wn * TNW + j * 8 + g;
                bf[j][0] = f2tf32(bs[n * STR + kk + tg]);
                bf[j][1] = f2tf32(bs[n * STR + kk + tg + 4]);
            }
#pragma unroll
            for (int i = 0; i < 4; i++)
#pragma unroll
                for (int j = 0; j < TNT; j++) {
                    float* c = acc[i][j];
                    asm volatile(
                        "mma.sync.aligned.m16n8k8.row.col.f32.tf32.tf32.f32 "
                        "{%0,%1,%2,%3}, {%4,%5,%6,%7}, {%8,%9}, {%0,%1,%2,%3};"
                        : "+f"(c[0]), "+f"(c[1]), "+f"(c[2]), "+f"(c[3])
                        : "r"(af[i][0]), "r"(af[i][1]), "r"(af[i][2]), "r"(af[i][3]),
                          "r"(bf[j][0]), "r"(bf[j][1]));
                }
        }
        __syncthreads();
    }

    // epilogue
#pragma unroll
    for (int i = 0; i < 4; i++) {
        long long r0 = (long long)blockIdx.y * BM + wm * 64 + i * 16 + g;
#pragma unroll
        for (int j = 0; j < TNT; j++) {
            int col = blockIdx.x * BN + wn * TNW + j * 8 + tg * 2;
            float2 lo = make_float2(alpha * acc[i][j][0], alpha * acc[i][j][1]);
            float2 hi = make_float2(alpha * acc[i][j][2], alpha * acc[i][j][3]);
            *(float2*)(C + r0 * ldc + col)       = lo;
            *(float2*)(C + (r0 + 8) * ldc + col) = hi;
        }
    }
}

// ---------------- per-head V transpose: Vt[bh][d][s] = V[b*S+s][h*64+d] ----
__global__ void __launch_bounds__(256)
transpose_v(const float* __restrict__ v, float* __restrict__ vt)
{
    __shared__ float tile[32][33];
    int bh = blockIdx.z;
    int b = bh >> 4, h = bh & 15;
    int s0 = blockIdx.x * 32, d0 = blockIdx.y * 32;
    int tx = threadIdx.x, ty = threadIdx.y;

    const float* src = v + (long long)b * SEQ * D_MODEL + h * DK;
#pragma unroll
    for (int i = ty; i < 32; i += 8)
        tile[i][tx] = src[(long long)(s0 + i) * D_MODEL + d0 + tx];
    __syncthreads();
    float* dst = vt + (long long)bh * DK * SEQ;
#pragma unroll
    for (int i = ty; i < 32; i += 8)
        dst[(long long)(d0 + i) * SEQ + s0 + tx] = tile[tx][i];
}

// ---------------- row softmax over 2048 elems ------------------------------
// Reads raw scores from s, writes normalized attn to dst (may alias s).
__global__ void __launch_bounds__(256)
softmax_rows(const float* __restrict__ s, float* __restrict__ dst)
{
    long long row = blockIdx.x;
    const float4* p4 = (const float4*)(s + row * SEQ);
    int tid = threadIdx.x;

    float4 e0 = p4[tid];
    float4 e1 = p4[tid + 256];

    float m = fmaxf(fmaxf(fmaxf(e0.x, e0.y), fmaxf(e0.z, e0.w)),
                    fmaxf(fmaxf(e1.x, e1.y), fmaxf(e1.z, e1.w)));
    m = blockReduceMax(m);

    e0.x = expf(e0.x - m); e0.y = expf(e0.y - m);
    e0.z = expf(e0.z - m); e0.w = expf(e0.w - m);
    e1.x = expf(e1.x - m); e1.y = expf(e1.y - m);
    e1.z = expf(e1.z - m); e1.w = expf(e1.w - m);

    float sum = e0.x + e0.y + e0.z + e0.w + e1.x + e1.y + e1.z + e1.w;
    sum = blockReduceSum(sum);
    float inv = 1.0f / sum;

    e0.x *= inv; e0.y *= inv; e0.z *= inv; e0.w *= inv;
    e1.x *= inv; e1.y *= inv; e1.z *= inv; e1.w *= inv;

    float4* a4 = (float4*)(dst + row * SEQ);
    a4[tid]       = e0;
    a4[tid + 256] = e1;
}

// ---------------- bias + residual + LayerNorm ------------------------------
__global__ void __launch_bounds__(256)
bias_res_ln(const float* __restrict__ o, const float* __restrict__ x,
            const float* __restrict__ bo, const float* __restrict__ gamma,
            const float* __restrict__ beta, float* __restrict__ y)
{
    long long row = blockIdx.x;
    int tid = threadIdx.x;
    const float4* o4 = (const float4*)(o + row * D_MODEL);
    const float4* x4 = (const float4*)(x + row * D_MODEL);
    const float4* b4 = (const float4*)bo;
    const float4* g4 = (const float4*)gamma;
    const float4* be4 = (const float4*)beta;

    float4 ov = o4[tid], xv = x4[tid], bv = b4[tid];
    float4 v;
    v.x = ov.x + xv.x + bv.x;
    v.y = ov.y + xv.y + bv.y;
    v.z = ov.z + xv.z + bv.z;
    v.w = ov.w + xv.w + bv.w;

    float s  = v.x + v.y + v.z + v.w;
    float sq = v.x * v.x + v.y * v.y + v.z * v.z + v.w * v.w;
    s  = blockReduceSum(s);
    sq = blockReduceSum(sq);

    float mean = s * (1.0f / D_MODEL);
    float var  = sq * (1.0f / D_MODEL) - mean * mean;
    float rstd = rsqrtf(var + LN_EPS);

    float4 gv = g4[tid], bev = be4[tid];
    float4 r;
    r.x = (v.x - mean) * rstd * gv.x + bev.x;
    r.y = (v.y - mean) * rstd * gv.y + bev.y;
    r.z = (v.z - mean) * rstd * gv.z + bev.z;
    r.w = (v.w - mean) * rstd * gv.w + bev.w;
    ((float4*)(y + row * D_MODEL))[tid] = r;
}

// ---------------- launch ---------------------------------------------------
extern "C" void kernel_launch(void* const* d_in, const int* in_sizes, int n_in,
                              void* d_out, int out_size)
{
    const float* x     = (const float*)d_in[0];
    const float* Wq    = (const float*)d_in[1];
    const float* Wk    = (const float*)d_in[2];
    const float* Wv    = (const float*)d_in[3];
    const float* Wo    = (const float*)d_in[4];
    const float* bo    = (const float*)d_in[5];
    const float* gamma = (const float*)d_in[6];
    const float* beta  = (const float*)d_in[7];

    float* y_out    = (float*)d_out;
    float* attn_out = nullptr;
    if ((long long)out_size >= SY + SA) {
        attn_out = y_out + SY;                 // outputs concatenated: y, attn
    } else if ((long long)out_size == SA) {
        attn_out = y_out;                      // attn-only output
        y_out = nullptr;
    }

    float *q, *k, *v, *ctx, *ob, *sc;
    cudaGetSymbolAddress((void**)&q,   g_q);
    cudaGetSymbolAddress((void**)&k,   g_k);
    cudaGetSymbolAddress((void**)&v,   g_v);
    cudaGetSymbolAddress((void**)&ctx, g_ctx);
    cudaGetSymbolAddress((void**)&ob,  g_o);
    cudaGetSymbolAddress((void**)&sc,  g_sc);

    float* attn = attn_out ? attn_out : sc;    // where normalized attn lives
    float* vt   = k;                           // reuse K buffer for V^T

    dim3 blk(256);
    const long long SBH = (long long)SEQ * D_MODEL;   // per-batch stride q/k/v/ctx
    const long long SSC = (long long)SEQ * SEQ;       // per-head stride in scores

    // Q/K/V projections: [4096,1024] = x @ W^T
    gemm_nt_tf32<128><<<dim3(8, 32, 1), blk>>>(ROWS, D_MODEL, D_MODEL,
        x, D_MODEL, 0, 0, Wq, D_MODEL, 0, 0, q, D_MODEL, 0, 0, 1.0f, 1);
    gemm_nt_tf32<128><<<dim3(8, 32, 1), blk>>>(ROWS, D_MODEL, D_MODEL,
        x, D_MODEL, 0, 0, Wk, D_MODEL, 0, 0, k, D_MODEL, 0, 0, 1.0f, 1);
    gemm_nt_tf32<128><<<dim3(8, 32, 1), blk>>>(ROWS, D_MODEL, D_MODEL,
        x, D_MODEL, 0, 0, Wv, D_MODEL, 0, 0, v, D_MODEL, 0, 0, 1.0f, 1);

    // scores[bh] = Q_bh @ K_bh^T / 8
    gemm_nt_tf32<128><<<dim3(16, 16, BATCH * N_HEADS), blk>>>(SEQ, SEQ, DK,
        q, D_MODEL, SBH, DK,
        k, D_MODEL, SBH, DK,
        sc, SEQ, (long long)N_HEADS * SSC, SSC,
        0.125f, N_HEADS);

    // transpose V per head: vt[bh][d][s]  (overwrites K buffer — K no longer needed)
    transpose_v<<<dim3(SEQ / 32, DK / 32, BATCH * N_HEADS), dim3(32, 8)>>>(v, vt);

    // softmax rows -> attn (normalized; this IS the attn output when present)
    softmax_rows<<<BATCH * N_HEADS * SEQ, blk>>>(sc, attn);

    // ctx[bh] = attn_bh @ vt_bh^T   (NT: B = Vt[dk rows, seq cols])
    gemm_nt_tf32<64><<<dim3(1, 16, BATCH * N_HEADS), blk>>>(SEQ, DK, SEQ,
        attn, SEQ, (long long)N_HEADS * SSC, SSC,
        vt, SEQ, (long long)N_HEADS * DK * SEQ, (long long)DK * SEQ,
        ctx, D_MODEL, SBH, DK,
        1.0f, N_HEADS);

    // output projection
    gemm_nt_tf32<128><<<dim3(8, 32, 1), blk>>>(ROWS, D_MODEL, D_MODEL,
        ctx, D_MODEL, 0, 0, Wo, D_MODEL, 0, 0, ob, D_MODEL, 0, 0, 1.0f, 1);

    // bias + residual + layernorm -> y
    if (y_out)
        bias_res_ln<<<ROWS, blk>>>(ob, x, bo, gamma, beta, y_out);
}